// round 6
// baseline (speedup 1.0000x reference)
#include <cuda_runtime.h>
#include <cuda_bf16.h>
#include <math.h>

// NeRFRenderer null-scattering marcher (max_depths=1): all tot replicas of a
// ray are identical -> single per-ray eval: ray-sphere hit, equirect env-map
// bilinear sample, attenuate.
//
// inputs: d_in[0] rays_o f32[N,3], d_in[1] rays_d f32[N,3],
//         d_in[2] env_map f32[1,3,16,32], d_in[3..4] step counts (cancel).
// output: f32 [N,3]
//
// R5: drop the per-CTA 6KB smem staging + __syncthreads. Each thread gathers
// its 12 needed env values (4 corners x 3 channels) directly via __ldg; the
// 6KB map lives in L2 across graph replays, so the gather is one overlapped
// ~L2-latency round-trip instead of DRAM-preload + block barrier + LDS.

#define ENV_H 16
#define ENV_W 32
#define ENV_HW (ENV_H * ENV_W)
#define SIGMA_MAJORANT 0.1f
#define PI_F 3.14159265358979323846f
#define THREADS 128

// fast acos, max err ~6.7e-5 rad
__device__ __forceinline__ float acos_fast(float x) {
    float ax = fabsf(x);
    float r = sqrtf(1.0f - ax) *
              (1.5707288f + ax * (-0.2121144f + ax * (0.0742610f + ax * (-0.0187293f))));
    return x < 0.0f ? (PI_F - r) : r;
}

// atan on [0,1], max err ~1e-5 rad
__device__ __forceinline__ float atan_poly(float a) {
    float s = a * a;
    return a * (0.9998660f + s * (-0.3302995f + s * (0.1801410f +
               s * (-0.0851330f + s * 0.0208351f))));
}

// fast atan2 (returns 0 at (0,0), matching nan_to_num in the reference)
__device__ __forceinline__ float atan2_fast(float y, float x) {
    float ay = fabsf(y), ax = fabsf(x);
    bool swap = ay > ax;
    float num = swap ? ax : ay;
    float den = swap ? ay : ax;
    den = fmaxf(den, 1e-30f);
    float r = atan_poly(__fdividef(num, den));
    if (swap) r = 1.57079632679f - r;
    if (x < 0.0f) r = PI_F - r;
    return y < 0.0f ? -r : r;
}

__global__ void __launch_bounds__(THREADS)
nerf_env_kernel(const float* __restrict__ rays_o,
                const float* __restrict__ rays_d,
                const float* __restrict__ env,
                float* __restrict__ out,
                int N)
{
    const int i = blockIdx.x * THREADS + threadIdx.x;
    if (i >= N) return;

    const float ox = rays_o[3 * i + 0];
    const float oy = rays_o[3 * i + 1];
    const float oz = rays_o[3 * i + 2];
    const float dx = rays_d[3 * i + 0];
    const float dy = rays_d[3 * i + 1];
    const float dz = rays_d[3 * i + 2];

    // ray-sphere (radius 1)
    const float a = dx * dx + dy * dy + dz * dz;
    const float c = ox * ox + oy * oy + oz * oz - 1.0f;
    const float b = 2.0f * (ox * dx + oy * dy + oz * dz);
    const float delta = b * b - 4.0f * a * c;
    const float sq = sqrtf(delta > 0.0f ? delta : 1.0f);
    const float t_hit = __fdividef(-b + sq, 2.0f * a);
    const bool valid = (delta > 0.0f) && (t_hit >= 0.0f);

    const float hx = ox + dx * t_hit;
    const float hy = oy + dy * t_hit;
    const float hz = oz + dz * t_hit;

    const float theta = atan2_fast(hx, -hz) * (1.0f / PI_F);      // grid y
    const float yc = fminf(fmaxf(hy, -1.0f + 1e-6f), 1.0f - 1e-6f);
    const float phi = (2.0f / PI_F) * acos_fast(yc) - 1.0f;       // grid x

    // grid_sample bilinear, align_corners=False, zero padding
    const float ix = ((phi   + 1.0f) * (float)ENV_W - 1.0f) * 0.5f;
    const float iy = ((theta + 1.0f) * (float)ENV_H - 1.0f) * 0.5f;
    const float fx0 = floorf(ix);
    const float fy0 = floorf(iy);
    const float wx1 = ix - fx0;
    const float wy1 = iy - fy0;
    const int x0 = (int)fx0;
    const int y0 = (int)fy0;

    const int   xs[2]  = {x0, x0 + 1};
    const int   ys[2]  = {y0, y0 + 1};
    const float wxs[2] = {1.0f - wx1, wx1};
    const float wys[2] = {1.0f - wy1, wy1};

    float acc0 = 0.0f, acc1 = 0.0f, acc2 = 0.0f;
#pragma unroll
    for (int jy = 0; jy < 2; jy++) {
#pragma unroll
        for (int jx = 0; jx < 2; jx++) {
            const int xcc = xs[jx];
            const int ycc = ys[jy];
            const bool inb = (xcc >= 0) && (xcc <= ENV_W - 1) &&
                             (ycc >= 0) && (ycc <= ENV_H - 1);
            const float w = wxs[jx] * wys[jy] * (inb ? 1.0f : 0.0f);
            const int xi = min(max(xcc, 0), ENV_W - 1);
            const int yi = min(max(ycc, 0), ENV_H - 1);
            const int base = yi * ENV_W + xi;
            acc0 = fmaf(w, __ldg(env + base),               acc0);
            acc1 = fmaf(w, __ldg(env + ENV_HW + base),      acc1);
            acc2 = fmaf(w, __ldg(env + 2 * ENV_HW + base),  acc2);
        }
    }

    const float st = SIGMA_MAJORANT * t_hit;
    out[3 * i + 0] = valid ? __expf(acc0 - st) : 0.0f;
    out[3 * i + 1] = valid ? __expf(acc1 - st) : 0.0f;
    out[3 * i + 2] = valid ? __expf(acc2 - st) : 0.0f;
}

extern "C" void kernel_launch(void* const* d_in, const int* in_sizes, int n_in,
                              void* d_out, int out_size)
{
    const float* rays_o = (const float*)d_in[0];
    const float* rays_d = (const float*)d_in[1];
    const float* env    = (const float*)d_in[2];
    float* out = (float*)d_out;

    const int N = in_sizes[0] / 3;
    const int blocks = (N + THREADS - 1) / THREADS;
    nerf_env_kernel<<<blocks, THREADS>>>(rays_o, rays_d, env, out, N);
}

// round 7
// speedup vs baseline: 1.1813x; 1.1813x over previous
#include <cuda_runtime.h>
#include <cuda_bf16.h>
#include <math.h>

// NeRFRenderer null-scattering marcher (max_depths=1): all tot replicas of a
// ray are identical -> single per-ray eval: ray-sphere hit, equirect env-map
// bilinear sample, attenuate.
//
// inputs: d_in[0] rays_o f32[N,3], d_in[1] rays_d f32[N,3],
//         d_in[2] env_map f32[1,3,16,32], d_in[3..4] step counts (cancel).
// output: f32 [N,3]
//
// R6: revert to smem-staged env (R5's direct-L2 gathers regressed), but run
// 256 CTAs x 64 threads so 2 CTAs co-reside per SM: one CTA's post-barrier
// gather overlaps the other's env-load wait. Fold grid-sample affine into the
// angle math.

#define ENV_H 16
#define ENV_W 32
#define ENV_HW (ENV_H * ENV_W)
#define ENV_ELEMS (3 * ENV_HW)              // 1536 floats = 384 float4
#define SIGMA_MAJORANT 0.1f
#define PI_F 3.14159265358979323846f
#define THREADS 64
#define F4_PER_THREAD (ENV_ELEMS / 4 / THREADS)   // 6

// fast acos, max err ~6.7e-5 rad
__device__ __forceinline__ float acos_fast(float x) {
    float ax = fabsf(x);
    float r = sqrtf(1.0f - ax) *
              (1.5707288f + ax * (-0.2121144f + ax * (0.0742610f + ax * (-0.0187293f))));
    return x < 0.0f ? (PI_F - r) : r;
}

// atan on [0,1], max err ~1e-5 rad
__device__ __forceinline__ float atan_poly(float a) {
    float s = a * a;
    return a * (0.9998660f + s * (-0.3302995f + s * (0.1801410f +
               s * (-0.0851330f + s * 0.0208351f))));
}

// fast atan2 (returns 0 at (0,0), matching nan_to_num in the reference)
__device__ __forceinline__ float atan2_fast(float y, float x) {
    float ay = fabsf(y), ax = fabsf(x);
    bool swap = ay > ax;
    float num = swap ? ax : ay;
    float den = swap ? ay : ax;
    den = fmaxf(den, 1e-30f);
    float r = atan_poly(__fdividef(num, den));
    if (swap) r = 1.57079632679f - r;
    if (x < 0.0f) r = PI_F - r;
    return y < 0.0f ? -r : r;
}

__global__ void __launch_bounds__(THREADS, 2)
nerf_env_kernel(const float* __restrict__ rays_o,
                const float* __restrict__ rays_d,
                const float* __restrict__ env,
                float* __restrict__ out,
                int N)
{
    __shared__ float s_env[ENV_ELEMS];

    const int i = blockIdx.x * THREADS + threadIdx.x;
    const bool active = (i < N);
    const int ii = active ? i : 0;
    const int t = threadIdx.x;

    // issue ray loads first
    const float ox = rays_o[3 * ii + 0];
    const float oy = rays_o[3 * ii + 1];
    const float oz = rays_o[3 * ii + 2];
    const float dx = rays_d[3 * ii + 0];
    const float dy = rays_d[3 * ii + 1];
    const float dz = rays_d[3 * ii + 2];

    // issue env preload: 384 float4 total, 6 per thread
    const float4* __restrict__ env4 = (const float4*)env;
    float4 e[F4_PER_THREAD];
#pragma unroll
    for (int k = 0; k < F4_PER_THREAD; k++)
        e[k] = env4[t + k * THREADS];

    // ---- env-independent math (overlaps the load latency above) ----
    const float a = dx * dx + dy * dy + dz * dz;
    const float c = ox * ox + oy * oy + oz * oz - 1.0f;
    const float b = 2.0f * (ox * dx + oy * dy + oz * dz);
    const float delta = b * b - 4.0f * a * c;
    const float sq = sqrtf(delta > 0.0f ? delta : 1.0f);
    const float t_hit = __fdividef(-b + sq, 2.0f * a);
    const bool valid = (delta > 0.0f) && (t_hit >= 0.0f);

    const float hx = ox + dx * t_hit;
    const float hy = oy + dy * t_hit;
    const float hz = oz + dz * t_hit;

    // grid-sample coords with the affine folded in:
    //   iy = ((theta+1)*H-1)/2 = (H/2)*theta + (H-1)/2,  theta = atan2/pi
    //   ix = ((phi+1)*W-1)/2   = (W/pi)*acos(yc) - 0.5
    const float iy = atan2_fast(hx, -hz) * ((float)ENV_H * 0.5f / PI_F)
                   + ((float)ENV_H - 1.0f) * 0.5f;
    const float yc = fminf(fmaxf(hy, -1.0f + 1e-6f), 1.0f - 1e-6f);
    const float ix = acos_fast(yc) * ((float)ENV_W / PI_F) - 0.5f;

    const float fx0 = floorf(ix);
    const float fy0 = floorf(iy);
    const float wx1 = ix - fx0;
    const float wy1 = iy - fy0;
    const int x0 = (int)fx0;
    const int y0 = (int)fy0;

    const int   xs[2]  = {x0, x0 + 1};
    const int   ys[2]  = {y0, y0 + 1};
    const float wxs[2] = {1.0f - wx1, wx1};
    const float wys[2] = {1.0f - wy1, wy1};

    // ---- commit env to smem, sync, gather ----
    float4* s_env4 = (float4*)s_env;
#pragma unroll
    for (int k = 0; k < F4_PER_THREAD; k++)
        s_env4[t + k * THREADS] = e[k];
    __syncthreads();

    float acc0 = 0.0f, acc1 = 0.0f, acc2 = 0.0f;
#pragma unroll
    for (int jy = 0; jy < 2; jy++) {
#pragma unroll
        for (int jx = 0; jx < 2; jx++) {
            const int xcc = xs[jx];
            const int ycc = ys[jy];
            const bool inb = (xcc >= 0) && (xcc <= ENV_W - 1) &&
                             (ycc >= 0) && (ycc <= ENV_H - 1);
            const float w = wxs[jx] * wys[jy] * (inb ? 1.0f : 0.0f);
            const int xi = min(max(xcc, 0), ENV_W - 1);
            const int yi = min(max(ycc, 0), ENV_H - 1);
            const int base = yi * ENV_W + xi;
            acc0 = fmaf(w, s_env[base],               acc0);
            acc1 = fmaf(w, s_env[ENV_HW + base],      acc1);
            acc2 = fmaf(w, s_env[2 * ENV_HW + base],  acc2);
        }
    }

    if (active) {
        const float st = SIGMA_MAJORANT * t_hit;
        out[3 * i + 0] = valid ? __expf(acc0 - st) : 0.0f;
        out[3 * i + 1] = valid ? __expf(acc1 - st) : 0.0f;
        out[3 * i + 2] = valid ? __expf(acc2 - st) : 0.0f;
    }
}

extern "C" void kernel_launch(void* const* d_in, const int* in_sizes, int n_in,
                              void* d_out, int out_size)
{
    const float* rays_o = (const float*)d_in[0];
    const float* rays_d = (const float*)d_in[1];
    const float* env    = (const float*)d_in[2];
    float* out = (float*)d_out;

    const int N = in_sizes[0] / 3;
    const int blocks = (N + THREADS - 1) / THREADS;
    nerf_env_kernel<<<blocks, THREADS>>>(rays_o, rays_d, env, out, N);
}